// round 5
// baseline (speedup 1.0000x reference)
#include <cuda_runtime.h>
#include <cuda_bf16.h>
#include <stdint.h>

#define B_TOT 32768
#define N_DIM 512
#define SOLVE_BLOCKS 32
#define SOLVE_ITERS 16
#define SPLITS 32
#define KSPLIT (B_TOT / SPLITS)
#define NPAIRS 10

// ------------- device scratch (no allocations allowed) -------------
__device__ __nv_bfloat16 g_R[(size_t)B_TOT * N_DIM];  // 32 MB bf16 r
__device__ float g_v[N_DIM];
__device__ float g_p[2][N_DIM];
__device__ float g_colsum[N_DIM];
__device__ double g_second;
__device__ unsigned g_bar_count, g_bar_gen;

__constant__ int c_pi[NPAIRS] = {0,0,0,0,1,1,1,2,2,3};
__constant__ int c_pj[NPAIRS] = {0,1,2,3,1,2,3,2,3,3};

// ------------------------------ init ------------------------------
__global__ void init_k() {
    int t = threadIdx.x;
    if (t < N_DIM) g_colsum[t] = 0.f;
    if (t == 0) { g_second = 0.0; g_bar_count = 0u; g_bar_gen = 0u; }
}

// -------------------- grid barrier (32 blocks) --------------------
__device__ __forceinline__ void grid_barrier(unsigned target) {
    __syncthreads();
    if (threadIdx.x == 0) {
        __threadfence();
        if (atomicAdd(&g_bar_count, 1u) == SOLVE_BLOCKS - 1) {
            atomicExch(&g_bar_count, 0u);
            __threadfence();
            atomicExch(&g_bar_gen, target);
        } else {
            while (atomicAdd(&g_bar_gen, 0u) < target) __nanosleep(64);
        }
    }
    __syncthreads();
}

// ---------- Chebyshev solve: v = Gamma^{-1} SR, spec in [1,5.6] ----------
__global__ void solve_k(const float* __restrict__ Gamma, const float* __restrict__ SR) {
    __shared__ float p_s[N_DIM];
    const int tid = threadIdx.x;
    const int w = tid >> 5, lane = tid & 31;
    const float lmin = 1.0f, lmax = 5.6f;
    const float theta = 0.5f * (lmax + lmin);  // 3.3
    const float delta = 0.5f * (lmax - lmin);  // 2.3
    const float sigma1 = theta / delta;
    float rho = 1.f / sigma1;
    const int row0 = blockIdx.x * 16 + w * 2;  // 2 rows per warp

    float xv[2], rv[2], dv[2];
#pragma unroll
    for (int q = 0; q < 2; q++) {
        float b = SR[row0 + q];
        rv[q] = b; xv[q] = 0.f; dv[q] = b / theta;
        if (lane == 0) __stcg(&g_p[0][row0 + q], dv[q]);
    }
    unsigned gen = 0;
    for (int it = 0; it < SOLVE_ITERS; it++) {
        grid_barrier(++gen);
        int cur = it & 1;
        for (int j = tid; j < N_DIM; j += 256) p_s[j] = __ldcg(&g_p[cur][j]);
        __syncthreads();
#pragma unroll
        for (int q = 0; q < 2; q++) {
            const float4* gr = (const float4*)(Gamma + (size_t)(row0 + q) * N_DIM);
            const float4* pr = (const float4*)p_s;
            float acc = 0.f;
#pragma unroll
            for (int tv = 0; tv < 4; tv++) {
                float4 g  = gr[lane + tv * 32];
                float4 p4 = pr[lane + tv * 32];
                acc += g.x * p4.x + g.y * p4.y + g.z * p4.z + g.w * p4.w;
            }
#pragma unroll
            for (int o = 16; o > 0; o >>= 1) acc += __shfl_xor_sync(0xffffffffu, acc, o);
            xv[q] += dv[q];   // x_{k+1} = x_k + d_k
            rv[q] -= acc;     // r_{k+1} = r_k - A d_k
        }
        float rho_n = 1.f / (2.f * sigma1 - rho);
#pragma unroll
        for (int q = 0; q < 2; q++) {
            dv[q] = rho_n * rho * dv[q] + (2.f * rho_n / delta) * rv[q];
            if (lane == 0 && it + 1 < SOLVE_ITERS) __stcg(&g_p[cur ^ 1][row0 + q], dv[q]);
        }
        rho = rho_n;
    }
    if (lane == 0) { g_v[row0] = xv[0]; g_v[row0 + 1] = xv[1]; }
}

// ---------- pass1: r = exp(sig - lsh); store bf16 R; column sums ----------
__global__ void pass1_k(const float* __restrict__ lsh, const float* __restrict__ sig) {
    const int t = threadIdx.x;         // 128 threads, thread t -> cols 4t..4t+3
    const int row0 = blockIdx.x * 16;  // 2048 blocks x 16 rows
    float cs0 = 0.f, cs1 = 0.f, cs2 = 0.f, cs3 = 0.f;
    for (int r = 0; r < 16; r++) {
        size_t off = (size_t)(row0 + r) * N_DIM + t * 4;
        float4 a = *(const float4*)(lsh + off);
        float4 b = *(const float4*)(sig + off);
        float r0 = __expf(b.x - a.x), r1 = __expf(b.y - a.y);
        float r2 = __expf(b.z - a.z), r3 = __expf(b.w - a.w);
        cs0 += r0; cs1 += r1; cs2 += r2; cs3 += r3;
        __nv_bfloat162 h0 = __floats2bfloat162_rn(r0, r1);
        __nv_bfloat162 h1 = __floats2bfloat162_rn(r2, r3);
        uint2 u;
        u.x = *reinterpret_cast<unsigned*>(&h0);
        u.y = *reinterpret_cast<unsigned*>(&h1);
        *reinterpret_cast<uint2*>(&g_R[off]) = u;
    }
    atomicAdd(&g_colsum[t * 4 + 0], cs0);
    atomicAdd(&g_colsum[t * 4 + 1], cs1);
    atomicAdd(&g_colsum[t * 4 + 2], cs2);
    atomicAdd(&g_colsum[t * 4 + 3], cs3);
}

// -------------------------- GEMM helpers --------------------------
__device__ __forceinline__ void cp16(void* smem, const void* gmem) {
    unsigned saddr = (unsigned)__cvta_generic_to_shared(smem);
    asm volatile("cp.async.cg.shared.global [%0], [%1], 16;\n" :: "r"(saddr), "l"(gmem));
}
__device__ __forceinline__ void ldsm4t(unsigned& d0, unsigned& d1, unsigned& d2, unsigned& d3,
                                       const __nv_bfloat16* p) {
    unsigned a = (unsigned)__cvta_generic_to_shared(p);
    asm volatile("ldmatrix.sync.aligned.m8n8.x4.trans.shared.b16 {%0,%1,%2,%3}, [%4];\n"
                 : "=r"(d0), "=r"(d1), "=r"(d2), "=r"(d3) : "r"(a));
}
__device__ __forceinline__ void mma16816(float* c, const unsigned* a, const unsigned* b) {
    asm volatile(
        "mma.sync.aligned.m16n8k16.row.col.f32.bf16.bf16.f32 "
        "{%0,%1,%2,%3}, {%4,%5,%6,%7}, {%8,%9}, {%0,%1,%2,%3};\n"
        : "+f"(c[0]), "+f"(c[1]), "+f"(c[2]), "+f"(c[3])
        : "r"(a[0]), "r"(a[1]), "r"(a[2]), "r"(a[3]), "r"(b[0]), "r"(b[1]));
}

// ---- syrk S = R^T R, epilogue folds sum_ij Gamma_ij v_i v_j S_ij ----
__global__ void __launch_bounds__(256, 2) gemm_k(const float* __restrict__ Gamma) {
    __shared__ __align__(16) __nv_bfloat16 smA[2][32][136];
    __shared__ __align__(16) __nv_bfloat16 smB[2][32][136];
    __shared__ double wsum[8];

    const int pair  = blockIdx.x % NPAIRS;
    const int split = blockIdx.x / NPAIRS;
    const int ti = c_pi[pair] * 128, tj = c_pj[pair] * 128;
    const int k0 = split * KSPLIT;

    const int tid  = threadIdx.x;
    const int lane = tid & 31, wid = tid >> 5;
    const int wi = wid >> 2, wj = wid & 3;   // warp tile 64(i) x 32(j)

    float acc[4][4][4];
#pragma unroll
    for (int a = 0; a < 4; a++)
#pragma unroll
        for (int b = 0; b < 4; b++)
#pragma unroll
            for (int e = 0; e < 4; e++) acc[a][b][e] = 0.f;

    auto load_stage = [&](int s, int buf) {
        int kbase = k0 + s * 32;
#pragma unroll
        for (int q = 0; q < 2; q++) {
            int idx = tid + q * 256;
            int row = idx >> 4, ch = idx & 15;
            const __nv_bfloat16* gbase = g_R + (size_t)(kbase + row) * N_DIM + ch * 8;
            cp16(&smA[buf][row][ch * 8], gbase + ti);
            cp16(&smB[buf][row][ch * 8], gbase + tj);
        }
    };

    const int NST = KSPLIT / 32;  // 32 stages
    load_stage(0, 0); asm volatile("cp.async.commit_group;\n");
    load_stage(1, 1); asm volatile("cp.async.commit_group;\n");

    const int g = lane >> 3, r = lane & 7;
    for (int s = 0; s < NST; s++) {
        asm volatile("cp.async.wait_group 1;\n");
        __syncthreads();
        int buf = s & 1;
#pragma unroll
        for (int ks = 0; ks < 2; ks++) {
            int kk = ks * 16;
            unsigned afr[4][4], bfr[4][2];
#pragma unroll
            for (int mt = 0; mt < 4; mt++) {
                int i0 = wi * 64 + mt * 16;
                const __nv_bfloat16* p = &smA[buf][kk + ((g >> 1) << 3) + r][i0 + ((g & 1) << 3)];
                ldsm4t(afr[mt][0], afr[mt][1], afr[mt][2], afr[mt][3], p);
            }
#pragma unroll
            for (int n2 = 0; n2 < 2; n2++) {
                int j0 = wj * 32 + n2 * 16;
                const __nv_bfloat16* p = &smB[buf][kk + ((g & 1) << 3) + r][j0 + ((g >> 1) << 3)];
                unsigned d0, d1, d2, d3;
                ldsm4t(d0, d1, d2, d3, p);
                bfr[n2 * 2][0] = d0; bfr[n2 * 2][1] = d1;
                bfr[n2 * 2 + 1][0] = d2; bfr[n2 * 2 + 1][1] = d3;
            }
#pragma unroll
            for (int mt = 0; mt < 4; mt++)
#pragma unroll
                for (int nt = 0; nt < 4; nt++) mma16816(acc[mt][nt], afr[mt], bfr[nt]);
        }
        __syncthreads();
        if (s + 2 < NST) load_stage(s + 2, buf);
        asm volatile("cp.async.commit_group;\n");
    }

    // epilogue: partial = sum Gamma_ij v_i v_j C_ij over this CTA's tile
    float partf = 0.f;
#pragma unroll
    for (int mt = 0; mt < 4; mt++) {
        int ibase = ti + wi * 64 + mt * 16 + (lane >> 2);
#pragma unroll
        for (int nt = 0; nt < 4; nt++) {
            int jbase = tj + wj * 32 + nt * 8 + 2 * (lane & 3);
#pragma unroll
            for (int e = 0; e < 4; e++) {
                int i = ibase + ((e >> 1) << 3);
                int j = jbase + (e & 1);
                partf += acc[mt][nt][e] * Gamma[(size_t)i * N_DIM + j] * g_v[i] * g_v[j];
            }
        }
    }
#pragma unroll
    for (int o = 16; o > 0; o >>= 1) partf += __shfl_xor_sync(0xffffffffu, partf, o);
    if (lane == 0) wsum[wid] = (double)partf;
    __syncthreads();
    if (tid == 0) {
        double s = 0.0;
        for (int x = 0; x < 8; x++) s += wsum[x];
        if (ti != tj) s *= 2.0;   // off-diagonal tiles counted twice (symmetry)
        atomicAdd(&g_second, s);
    }
}

// ------------------------------ combine ------------------------------
__global__ void combine_k(const float* __restrict__ SR, const int* __restrict__ kp,
                          float* __restrict__ out) {
    __shared__ double ws[16];
    int t = threadIdx.x;  // 512
    double term = (double)g_colsum[t] * (double)g_v[t] * (double)SR[t];
#pragma unroll
    for (int o = 16; o > 0; o >>= 1) term += __shfl_xor_sync(0xffffffffu, term, o);
    if ((t & 31) == 0) ws[t >> 5] = term;
    __syncthreads();
    if (t == 0) {
        double sf = 0.0;
        for (int x = 0; x < 16; x++) sf += ws[x];
        double k = (double)kp[0];
        out[0] = (float)((0.5 * g_second - sf) / ((double)B_TOT * k));
    }
}

// ------------------------------ launch ------------------------------
extern "C" void kernel_launch(void* const* d_in, const int* in_sizes, int n_in,
                              void* d_out, int out_size) {
    const float* lsh = (const float*)d_in[0];
    const float* sig = (const float*)d_in[1];
    const float* SR  = (const float*)d_in[2];
    const float* Gam = (const float*)d_in[3];
    const int*   kp  = (const int*)d_in[4];

    init_k<<<1, 512>>>();
    solve_k<<<SOLVE_BLOCKS, 256>>>(Gam, SR);
    pass1_k<<<B_TOT / 16, 128>>>(lsh, sig);
    gemm_k<<<NPAIRS * SPLITS, 256>>>(Gam);
    combine_k<<<1, 512>>>(SR, kp, (float*)d_out);
}

// round 6
// speedup vs baseline: 1.1569x; 1.1569x over previous
#include <cuda_runtime.h>
#include <cuda_bf16.h>
#include <stdint.h>

#define B_TOT 32768
#define N_DIM 512
#define SOLVE_BLOCKS 32
#define SOLVE_ITERS 12
#define SPLITS 29
#define NPAIRS 10
#define NCTAS (NPAIRS * SPLITS)
#define TOT_STAGES (B_TOT / 32)   // 1024

// ------------- device scratch (no allocations allowed) -------------
__device__ __nv_bfloat16 g_R[(size_t)B_TOT * N_DIM];  // 32 MB bf16 r
__device__ float g_v[N_DIM];
__device__ float g_p[2][N_DIM];
__device__ float g_colsum[N_DIM];
__device__ double g_second;
__device__ unsigned g_bar_count, g_bar_gen, g_done;

__constant__ int c_pi[NPAIRS] = {0,0,0,0,1,1,1,2,2,3};
__constant__ int c_pj[NPAIRS] = {0,1,2,3,1,2,3,2,3,3};

// ------------------------------ init ------------------------------
__global__ void init_k() {
    int t = threadIdx.x;
    if (t < N_DIM) g_colsum[t] = 0.f;
    if (t == 0) { g_second = 0.0; g_bar_count = 0u; g_bar_gen = 0u; g_done = 0u; }
}

// -------------------- grid barrier (32 blocks) --------------------
__device__ __forceinline__ void grid_barrier(unsigned target) {
    __syncthreads();
    if (threadIdx.x == 0) {
        __threadfence();
        if (atomicAdd(&g_bar_count, 1u) == SOLVE_BLOCKS - 1) {
            atomicExch(&g_bar_count, 0u);
            __threadfence();
            atomicExch(&g_bar_gen, target);
        } else {
            while (atomicAdd(&g_bar_gen, 0u) < target) __nanosleep(32);
        }
    }
    __syncthreads();
}

// ---------- Chebyshev solve: v = Gamma^{-1} SR, spec in [1,5.6] ----------
__global__ void solve_k(const float* __restrict__ Gamma, const float* __restrict__ SR) {
    __shared__ float p_s[N_DIM];
    const int tid = threadIdx.x;
    const int w = tid >> 5, lane = tid & 31;
    const float lmin = 1.0f, lmax = 5.6f;
    const float theta = 0.5f * (lmax + lmin);
    const float delta = 0.5f * (lmax - lmin);
    const float sigma1 = theta / delta;
    float rho = 1.f / sigma1;
    const int row0 = blockIdx.x * 16 + w * 2;  // 2 rows per warp (8 warps x 2)

    float xv[2], rv[2], dv[2];
#pragma unroll
    for (int q = 0; q < 2; q++) {
        float b = SR[row0 + q];
        rv[q] = b; xv[q] = 0.f; dv[q] = b / theta;
        if (lane == 0) __stcg(&g_p[0][row0 + q], dv[q]);
    }
    unsigned gen = 0;
    for (int it = 0; it < SOLVE_ITERS; it++) {
        grid_barrier(++gen);
        int cur = it & 1;
        for (int j = tid; j < N_DIM; j += 256) p_s[j] = __ldcg(&g_p[cur][j]);
        __syncthreads();
#pragma unroll
        for (int q = 0; q < 2; q++) {
            const float4* gr = (const float4*)(Gamma + (size_t)(row0 + q) * N_DIM);
            const float4* pr = (const float4*)p_s;
            float acc = 0.f;
#pragma unroll
            for (int tv = 0; tv < 4; tv++) {
                float4 g  = gr[lane + tv * 32];
                float4 p4 = pr[lane + tv * 32];
                acc += g.x * p4.x + g.y * p4.y + g.z * p4.z + g.w * p4.w;
            }
#pragma unroll
            for (int o = 16; o > 0; o >>= 1) acc += __shfl_xor_sync(0xffffffffu, acc, o);
            xv[q] += dv[q];   // x_{k+1} = x_k + d_k
            rv[q] -= acc;     // r_{k+1} = r_k - A d_k
        }
        float rho_n = 1.f / (2.f * sigma1 - rho);
#pragma unroll
        for (int q = 0; q < 2; q++) {
            dv[q] = rho_n * rho * dv[q] + (2.f * rho_n / delta) * rv[q];
            if (lane == 0 && it + 1 < SOLVE_ITERS) __stcg(&g_p[cur ^ 1][row0 + q], dv[q]);
        }
        rho = rho_n;
    }
    if (lane == 0) { g_v[row0] = xv[0]; g_v[row0 + 1] = xv[1]; }
}

// ---------- pass1: r = exp(sig - lsh); store bf16 R; column sums ----------
__global__ void pass1_k(const float* __restrict__ lsh, const float* __restrict__ sig) {
    const int t = threadIdx.x;         // 128 threads, thread t -> cols 4t..4t+3
    const int row0 = blockIdx.x * 16;  // 2048 blocks x 16 rows
    float cs0 = 0.f, cs1 = 0.f, cs2 = 0.f, cs3 = 0.f;
    for (int r = 0; r < 16; r++) {
        size_t off = (size_t)(row0 + r) * N_DIM + t * 4;
        float4 a = __ldcs((const float4*)(lsh + off));   // read-once: evict-first
        float4 b = __ldcs((const float4*)(sig + off));
        float r0 = __expf(b.x - a.x), r1 = __expf(b.y - a.y);
        float r2 = __expf(b.z - a.z), r3 = __expf(b.w - a.w);
        cs0 += r0; cs1 += r1; cs2 += r2; cs3 += r3;
        __nv_bfloat162 h0 = __floats2bfloat162_rn(r0, r1);
        __nv_bfloat162 h1 = __floats2bfloat162_rn(r2, r3);
        uint2 u;
        u.x = *reinterpret_cast<unsigned*>(&h0);
        u.y = *reinterpret_cast<unsigned*>(&h1);
        *reinterpret_cast<uint2*>(&g_R[off]) = u;
    }
    atomicAdd(&g_colsum[t * 4 + 0], cs0);
    atomicAdd(&g_colsum[t * 4 + 1], cs1);
    atomicAdd(&g_colsum[t * 4 + 2], cs2);
    atomicAdd(&g_colsum[t * 4 + 3], cs3);
}

// -------------------------- GEMM helpers --------------------------
__device__ __forceinline__ void cp16(void* smem, const void* gmem) {
    unsigned saddr = (unsigned)__cvta_generic_to_shared(smem);
    asm volatile("cp.async.cg.shared.global [%0], [%1], 16;\n" :: "r"(saddr), "l"(gmem));
}
__device__ __forceinline__ void ldsm4t(unsigned& d0, unsigned& d1, unsigned& d2, unsigned& d3,
                                       const __nv_bfloat16* p) {
    unsigned a = (unsigned)__cvta_generic_to_shared(p);
    asm volatile("ldmatrix.sync.aligned.m8n8.x4.trans.shared.b16 {%0,%1,%2,%3}, [%4];\n"
                 : "=r"(d0), "=r"(d1), "=r"(d2), "=r"(d3) : "r"(a));
}
__device__ __forceinline__ void mma16816(float* c, const unsigned* a, const unsigned* b) {
    asm volatile(
        "mma.sync.aligned.m16n8k16.row.col.f32.bf16.bf16.f32 "
        "{%0,%1,%2,%3}, {%4,%5,%6,%7}, {%8,%9}, {%0,%1,%2,%3};\n"
        : "+f"(c[0]), "+f"(c[1]), "+f"(c[2]), "+f"(c[3])
        : "r"(a[0]), "r"(a[1]), "r"(a[2]), "r"(a[3]), "r"(b[0]), "r"(b[1]));
}

// ---- syrk S = R^T R; epilogue folds sum_ij Gamma_ij v_i v_j S_ij;
// ---- last-done CTA computes the final scalar (combine merged in) ----
__global__ void __launch_bounds__(256, 2) gemm_k(const float* __restrict__ Gamma,
                                                 const float* __restrict__ SR,
                                                 const int* __restrict__ kp,
                                                 float* __restrict__ out) {
    __shared__ __align__(16) __nv_bfloat16 smA[2][32][136];
    __shared__ __align__(16) __nv_bfloat16 smB[2][32][136];
    __shared__ double wsum[8];
    __shared__ bool is_last;

    const int pair  = blockIdx.x % NPAIRS;
    const int split = blockIdx.x / NPAIRS;          // 0..28
    const int ti = c_pi[pair] * 128, tj = c_pj[pair] * 128;
    const int s0 = (split * TOT_STAGES) / SPLITS;   // uneven stage ranges
    const int s1 = ((split + 1) * TOT_STAGES) / SPLITS;
    const int ns = s1 - s0;                         // 35 or 36

    const int tid  = threadIdx.x;
    const int lane = tid & 31, wid = tid >> 5;
    const int wi = wid >> 2, wj = wid & 3;          // warp tile 64(i) x 32(j)

    float acc[4][4][4];
#pragma unroll
    for (int a = 0; a < 4; a++)
#pragma unroll
        for (int b = 0; b < 4; b++)
#pragma unroll
            for (int e = 0; e < 4; e++) acc[a][b][e] = 0.f;

    auto load_stage = [&](int s, int buf) {
        int kbase = s * 32;
#pragma unroll
        for (int q = 0; q < 2; q++) {
            int idx = tid + q * 256;
            int row = idx >> 4, ch = idx & 15;
            const __nv_bfloat16* gbase = g_R + (size_t)(kbase + row) * N_DIM + ch * 8;
            cp16(&smA[buf][row][ch * 8], gbase + ti);
            cp16(&smB[buf][row][ch * 8], gbase + tj);
        }
    };

    load_stage(s0, 0); asm volatile("cp.async.commit_group;\n");
    load_stage(s0 + 1, 1); asm volatile("cp.async.commit_group;\n");

    const int g = lane >> 3, r = lane & 7;
    for (int s = 0; s < ns; s++) {
        asm volatile("cp.async.wait_group 1;\n");
        __syncthreads();
        int buf = s & 1;
#pragma unroll
        for (int ks = 0; ks < 2; ks++) {
            int kk = ks * 16;
            unsigned afr[4][4], bfr[4][2];
#pragma unroll
            for (int mt = 0; mt < 4; mt++) {
                int i0 = wi * 64 + mt * 16;
                const __nv_bfloat16* p = &smA[buf][kk + ((g >> 1) << 3) + r][i0 + ((g & 1) << 3)];
                ldsm4t(afr[mt][0], afr[mt][1], afr[mt][2], afr[mt][3], p);
            }
#pragma unroll
            for (int n2 = 0; n2 < 2; n2++) {
                int j0 = wj * 32 + n2 * 16;
                const __nv_bfloat16* p = &smB[buf][kk + ((g & 1) << 3) + r][j0 + ((g >> 1) << 3)];
                unsigned d0, d1, d2, d3;
                ldsm4t(d0, d1, d2, d3, p);
                bfr[n2 * 2][0] = d0; bfr[n2 * 2][1] = d1;
                bfr[n2 * 2 + 1][0] = d2; bfr[n2 * 2 + 1][1] = d3;
            }
#pragma unroll
            for (int mt = 0; mt < 4; mt++)
#pragma unroll
                for (int nt = 0; nt < 4; nt++) mma16816(acc[mt][nt], afr[mt], bfr[nt]);
        }
        __syncthreads();
        if (s + 2 < ns) load_stage(s0 + s + 2, buf);
        asm volatile("cp.async.commit_group;\n");
    }

    // epilogue: partial = sum Gamma_ij v_i v_j C_ij over this CTA's tile
    float partf = 0.f;
#pragma unroll
    for (int mt = 0; mt < 4; mt++) {
        int ibase = ti + wi * 64 + mt * 16 + (lane >> 2);
#pragma unroll
        for (int nt = 0; nt < 4; nt++) {
            int jbase = tj + wj * 32 + nt * 8 + 2 * (lane & 3);
#pragma unroll
            for (int e = 0; e < 4; e++) {
                int i = ibase + ((e >> 1) << 3);
                int j = jbase + (e & 1);
                partf += acc[mt][nt][e] * Gamma[(size_t)i * N_DIM + j] * g_v[i] * g_v[j];
            }
        }
    }
#pragma unroll
    for (int o = 16; o > 0; o >>= 1) partf += __shfl_xor_sync(0xffffffffu, partf, o);
    if (lane == 0) wsum[wid] = (double)partf;
    __syncthreads();
    if (tid == 0) {
        double s = 0.0;
        for (int x = 0; x < 8; x++) s += wsum[x];
        if (ti != tj) s *= 2.0;   // off-diagonal tiles counted twice (symmetry)
        atomicAdd(&g_second, s);
        __threadfence();
        unsigned d = atomicAdd(&g_done, 1u);
        is_last = (d == NCTAS - 1);
    }
    __syncthreads();

    // ---- last CTA computes the final scalar ----
    if (is_last) {
        double term = 0.0;
        for (int j = tid; j < N_DIM; j += 256)
            term += (double)g_colsum[j] * (double)g_v[j] * (double)SR[j];
#pragma unroll
        for (int o = 16; o > 0; o >>= 1) term += __shfl_xor_sync(0xffffffffu, term, o);
        if (lane == 0) wsum[wid] = term;
        __syncthreads();
        if (tid == 0) {
            double sf = 0.0;
            for (int x = 0; x < 8; x++) sf += wsum[x];
            double sec = atomicAdd(&g_second, 0.0);   // all writers fenced before g_done
            double k = (double)kp[0];
            out[0] = (float)((0.5 * sec - sf) / ((double)B_TOT * k));
        }
    }
}

// ------------------------------ launch ------------------------------
extern "C" void kernel_launch(void* const* d_in, const int* in_sizes, int n_in,
                              void* d_out, int out_size) {
    const float* lsh = (const float*)d_in[0];
    const float* sig = (const float*)d_in[1];
    const float* SR  = (const float*)d_in[2];
    const float* Gam = (const float*)d_in[3];
    const int*   kp  = (const int*)d_in[4];

    init_k<<<1, 512>>>();
    solve_k<<<SOLVE_BLOCKS, 256>>>(Gam, SR);
    pass1_k<<<B_TOT / 16, 128>>>(lsh, sig);
    gemm_k<<<NCTAS, 256>>>(Gam, SR, kp, (float*)d_out);
}

// round 7
// speedup vs baseline: 1.4435x; 1.2477x over previous
#include <cuda_runtime.h>
#include <cuda_bf16.h>
#include <stdint.h>

#define B_TOT 32768
#define N_DIM 512
#define SOLVE_BLOCKS 32
#define SOLVE_ITERS 10
#define PASS1_BLOCKS (B_TOT / 32)          // 1024 blocks, 32 rows each
#define FUSED_BLOCKS (SOLVE_BLOCKS + PASS1_BLOCKS)
#define SPLITS 29
#define NPAIRS 10
#define NCTAS (NPAIRS * SPLITS)            // 290 = single wave @ 2 CTA/SM
#define TOT_STAGES (B_TOT / 32)            // 1024

// ------------- device scratch (no allocations allowed) -------------
__device__ __nv_bfloat16 g_R[(size_t)B_TOT * N_DIM];  // 32 MB bf16 r
__device__ float g_v[N_DIM];
__device__ float g_p[2][N_DIM];
__device__ float g_colsum[N_DIM];
__device__ double g_second;
__device__ unsigned g_bar_count, g_bar_gen, g_done;

__constant__ int c_pi[NPAIRS] = {0,0,0,0,1,1,1,2,2,3};
__constant__ int c_pj[NPAIRS] = {0,1,2,3,1,2,3,2,3,3};

// ------------------------------ init ------------------------------
__global__ void init_k() {
    int t = threadIdx.x;
    if (t < N_DIM) g_colsum[t] = 0.f;
    if (t == 0) { g_second = 0.0; g_bar_count = 0u; g_bar_gen = 0u; g_done = 0u; }
}

// ---- grid barrier among the 32 solve blocks (uncontended ldcg poll) ----
__device__ __forceinline__ void grid_barrier(unsigned target) {
    __syncthreads();
    if (threadIdx.x == 0) {
        __threadfence();
        if (atomicAdd(&g_bar_count, 1u) == SOLVE_BLOCKS - 1) {
            atomicExch(&g_bar_count, 0u);
            __threadfence();
            atomicExch(&g_bar_gen, target);
        } else {
            while (__ldcg(&g_bar_gen) < target) __nanosleep(20);
        }
        __threadfence();
    }
    __syncthreads();
}

// ============ fused kernel: solve (blocks 0..31) + pass1 (rest) ============
// solve: Chebyshev for v = Gamma^{-1} SR, spectrum in [1, 5.5].
//        Gamma rows register-cached; per-iter cost ~ one barrier.
// pass1: r = exp(sig - lsh); store bf16 R; fp32 column sums.
__global__ void __launch_bounds__(256) fused_k(const float* __restrict__ Gamma,
                                               const float* __restrict__ SR,
                                               const float* __restrict__ lsh,
                                               const float* __restrict__ sig) {
    if (blockIdx.x < SOLVE_BLOCKS) {
        // ---------------- solve ----------------
        __shared__ float p_s[N_DIM];
        const int tid = threadIdx.x;
        const int w = tid >> 5, lane = tid & 31;
        const float lmin = 1.0f, lmax = 5.5f;
        const float theta = 0.5f * (lmax + lmin);   // 3.25
        const float delta = 0.5f * (lmax - lmin);   // 2.25
        const float sigma1 = theta / delta;
        float rho = 1.f / sigma1;
        const int row0 = blockIdx.x * 16 + w * 2;   // 2 rows per warp

        // register-cache this warp's 2 Gamma rows (32 floats/lane)
        float4 gc[2][4];
#pragma unroll
        for (int q = 0; q < 2; q++) {
            const float4* gr = (const float4*)(Gamma + (size_t)(row0 + q) * N_DIM);
#pragma unroll
            for (int tv = 0; tv < 4; tv++) gc[q][tv] = gr[lane + tv * 32];
        }

        float xv[2], rv[2], dv[2];
#pragma unroll
        for (int q = 0; q < 2; q++) {
            float b = SR[row0 + q];
            rv[q] = b; xv[q] = 0.f; dv[q] = b / theta;
            if (lane == 0) __stcg(&g_p[0][row0 + q], dv[q]);
        }
        unsigned gen = 0;
        for (int it = 0; it < SOLVE_ITERS; it++) {
            grid_barrier(++gen);
            int cur = it & 1;
            for (int j = tid; j < N_DIM; j += 256) p_s[j] = __ldcg(&g_p[cur][j]);
            __syncthreads();
#pragma unroll
            for (int q = 0; q < 2; q++) {
                const float4* pr = (const float4*)p_s;
                float acc = 0.f;
#pragma unroll
                for (int tv = 0; tv < 4; tv++) {
                    float4 g  = gc[q][tv];
                    float4 p4 = pr[lane + tv * 32];
                    acc += g.x * p4.x + g.y * p4.y + g.z * p4.z + g.w * p4.w;
                }
#pragma unroll
                for (int o = 16; o > 0; o >>= 1) acc += __shfl_xor_sync(0xffffffffu, acc, o);
                xv[q] += dv[q];   // x_{k+1} = x_k + d_k
                rv[q] -= acc;     // r_{k+1} = r_k - A d_k
            }
            float rho_n = 1.f / (2.f * sigma1 - rho);
#pragma unroll
            for (int q = 0; q < 2; q++) {
                dv[q] = rho_n * rho * dv[q] + (2.f * rho_n / delta) * rv[q];
                if (lane == 0 && it + 1 < SOLVE_ITERS) __stcg(&g_p[cur ^ 1][row0 + q], dv[q]);
            }
            rho = rho_n;
            __syncthreads();
        }
        if (lane == 0) { g_v[row0] = xv[0]; g_v[row0 + 1] = xv[1]; }
    } else {
        // ---------------- pass1 ----------------
        const int pb   = blockIdx.x - SOLVE_BLOCKS;
        const int tc   = threadIdx.x & 127;           // column group
        const int half = threadIdx.x >> 7;            // 0/1
        const int row0 = pb * 32 + half * 16;
        float cs0 = 0.f, cs1 = 0.f, cs2 = 0.f, cs3 = 0.f;
        for (int r = 0; r < 16; r++) {
            size_t off = (size_t)(row0 + r) * N_DIM + tc * 4;
            float4 a = __ldcs((const float4*)(lsh + off));   // read-once
            float4 b = __ldcs((const float4*)(sig + off));
            float r0 = __expf(b.x - a.x), r1 = __expf(b.y - a.y);
            float r2 = __expf(b.z - a.z), r3 = __expf(b.w - a.w);
            cs0 += r0; cs1 += r1; cs2 += r2; cs3 += r3;
            __nv_bfloat162 h0 = __floats2bfloat162_rn(r0, r1);
            __nv_bfloat162 h1 = __floats2bfloat162_rn(r2, r3);
            uint2 u;
            u.x = *reinterpret_cast<unsigned*>(&h0);
            u.y = *reinterpret_cast<unsigned*>(&h1);
            *reinterpret_cast<uint2*>(&g_R[off]) = u;
        }
        atomicAdd(&g_colsum[tc * 4 + 0], cs0);
        atomicAdd(&g_colsum[tc * 4 + 1], cs1);
        atomicAdd(&g_colsum[tc * 4 + 2], cs2);
        atomicAdd(&g_colsum[tc * 4 + 3], cs3);
    }
}

// -------------------------- GEMM helpers --------------------------
__device__ __forceinline__ void cp16(void* smem, const void* gmem) {
    unsigned saddr = (unsigned)__cvta_generic_to_shared(smem);
    asm volatile("cp.async.cg.shared.global [%0], [%1], 16;\n" :: "r"(saddr), "l"(gmem));
}
__device__ __forceinline__ void ldsm4t(unsigned& d0, unsigned& d1, unsigned& d2, unsigned& d3,
                                       const __nv_bfloat16* p) {
    unsigned a = (unsigned)__cvta_generic_to_shared(p);
    asm volatile("ldmatrix.sync.aligned.m8n8.x4.trans.shared.b16 {%0,%1,%2,%3}, [%4];\n"
                 : "=r"(d0), "=r"(d1), "=r"(d2), "=r"(d3) : "r"(a));
}
__device__ __forceinline__ void mma16816(float* c, const unsigned* a, const unsigned* b) {
    asm volatile(
        "mma.sync.aligned.m16n8k16.row.col.f32.bf16.bf16.f32 "
        "{%0,%1,%2,%3}, {%4,%5,%6,%7}, {%8,%9}, {%0,%1,%2,%3};\n"
        : "+f"(c[0]), "+f"(c[1]), "+f"(c[2]), "+f"(c[3])
        : "r"(a[0]), "r"(a[1]), "r"(a[2]), "r"(a[3]), "r"(b[0]), "r"(b[1]));
}

// ---- syrk S = R^T R; epilogue folds sum_ij Gamma_ij v_i v_j S_ij;
// ---- ring-4 cp.async pipeline, ONE syncthreads per stage;
// ---- last-done CTA computes the final scalar ----
__global__ void __launch_bounds__(256, 2) gemm_k(const float* __restrict__ Gamma,
                                                 const float* __restrict__ SR,
                                                 const int* __restrict__ kp,
                                                 float* __restrict__ out) {
    __shared__ __align__(16) __nv_bfloat16 smA[4][32][136];
    __shared__ __align__(16) __nv_bfloat16 smB[4][32][136];
    __shared__ double wsum[8];
    __shared__ bool is_last;

    const int pair  = blockIdx.x % NPAIRS;
    const int split = blockIdx.x / NPAIRS;          // 0..28
    const int ti = c_pi[pair] * 128, tj = c_pj[pair] * 128;
    const int s0 = (split * TOT_STAGES) / SPLITS;   // uneven stage ranges
    const int s1 = ((split + 1) * TOT_STAGES) / SPLITS;
    const int ns = s1 - s0;                         // 35 or 36

    const int tid  = threadIdx.x;
    const int lane = tid & 31, wid = tid >> 5;
    const int wi = wid >> 2, wj = wid & 3;          // warp tile 64(i) x 32(j)

    float acc[4][4][4];
#pragma unroll
    for (int a = 0; a < 4; a++)
#pragma unroll
        for (int b = 0; b < 4; b++)
#pragma unroll
            for (int e = 0; e < 4; e++) acc[a][b][e] = 0.f;

    auto load_stage = [&](int s, int buf) {
        int kbase = s * 32;
#pragma unroll
        for (int q = 0; q < 2; q++) {
            int idx = tid + q * 256;
            int row = idx >> 4, ch = idx & 15;
            const __nv_bfloat16* gbase = g_R + (size_t)(kbase + row) * N_DIM + ch * 8;
            cp16(&smA[buf][row][ch * 8], gbase + ti);
            cp16(&smB[buf][row][ch * 8], gbase + tj);
        }
    };

    load_stage(s0 + 0, 0); asm volatile("cp.async.commit_group;\n");
    load_stage(s0 + 1, 1); asm volatile("cp.async.commit_group;\n");
    load_stage(s0 + 2, 2); asm volatile("cp.async.commit_group;\n");

    const int g = lane >> 3, r = lane & 7;
    for (int s = 0; s < ns; s++) {
        asm volatile("cp.async.wait_group 2;\n");   // stage s resident
        __syncthreads();                            // buf (s+3)&3 free for rewrite
        if (s + 3 < ns) load_stage(s0 + s + 3, (s + 3) & 3);
        asm volatile("cp.async.commit_group;\n");   // empty commit at tail keeps count
        const int buf = s & 3;
#pragma unroll
        for (int ks = 0; ks < 2; ks++) {
            int kk = ks * 16;
            unsigned afr[4][4], bfr[4][2];
#pragma unroll
            for (int mt = 0; mt < 4; mt++) {
                int i0 = wi * 64 + mt * 16;
                const __nv_bfloat16* p = &smA[buf][kk + ((g >> 1) << 3) + r][i0 + ((g & 1) << 3)];
                ldsm4t(afr[mt][0], afr[mt][1], afr[mt][2], afr[mt][3], p);
            }
#pragma unroll
            for (int n2 = 0; n2 < 2; n2++) {
                int j0 = wj * 32 + n2 * 16;
                const __nv_bfloat16* p = &smB[buf][kk + ((g & 1) << 3) + r][j0 + ((g >> 1) << 3)];
                unsigned d0, d1, d2, d3;
                ldsm4t(d0, d1, d2, d3, p);
                bfr[n2 * 2][0] = d0; bfr[n2 * 2][1] = d1;
                bfr[n2 * 2 + 1][0] = d2; bfr[n2 * 2 + 1][1] = d3;
            }
#pragma unroll
            for (int mt = 0; mt < 4; mt++)
#pragma unroll
                for (int nt = 0; nt < 4; nt++) mma16816(acc[mt][nt], afr[mt], bfr[nt]);
        }
    }

    // epilogue: partial = sum Gamma_ij v_i v_j C_ij over this CTA's tile
    float partf = 0.f;
#pragma unroll
    for (int mt = 0; mt < 4; mt++) {
        int ibase = ti + wi * 64 + mt * 16 + (lane >> 2);
#pragma unroll
        for (int nt = 0; nt < 4; nt++) {
            int jbase = tj + wj * 32 + nt * 8 + 2 * (lane & 3);
#pragma unroll
            for (int e = 0; e < 4; e++) {
                int i = ibase + ((e >> 1) << 3);
                int j = jbase + (e & 1);
                partf += acc[mt][nt][e] * Gamma[(size_t)i * N_DIM + j] * g_v[i] * g_v[j];
            }
        }
    }
#pragma unroll
    for (int o = 16; o > 0; o >>= 1) partf += __shfl_xor_sync(0xffffffffu, partf, o);
    if (lane == 0) wsum[wid] = (double)partf;
    __syncthreads();
    if (tid == 0) {
        double s = 0.0;
        for (int x = 0; x < 8; x++) s += wsum[x];
        if (ti != tj) s *= 2.0;   // off-diagonal tiles counted twice (symmetry)
        atomicAdd(&g_second, s);
        __threadfence();
        unsigned d = atomicAdd(&g_done, 1u);
        is_last = (d == NCTAS - 1);
    }
    __syncthreads();

    // ---- last CTA computes the final scalar ----
    if (is_last) {
        double term = 0.0;
        for (int j = tid; j < N_DIM; j += 256)
            term += (double)g_colsum[j] * (double)g_v[j] * (double)SR[j];
#pragma unroll
        for (int o = 16; o > 0; o >>= 1) term += __shfl_xor_sync(0xffffffffu, term, o);
        if (lane == 0) wsum[wid] = term;
        __syncthreads();
        if (tid == 0) {
            double sf = 0.0;
            for (int x = 0; x < 8; x++) sf += wsum[x];
            double sec = atomicAdd(&g_second, 0.0);   // all writers fenced before g_done
            double k = (double)kp[0];
            out[0] = (float)((0.5 * sec - sf) / ((double)B_TOT * k));
        }
    }
}

// ------------------------------ launch ------------------------------
extern "C" void kernel_launch(void* const* d_in, const int* in_sizes, int n_in,
                              void* d_out, int out_size) {
    const float* lsh = (const float*)d_in[0];
    const float* sig = (const float*)d_in[1];
    const float* SR  = (const float*)d_in[2];
    const float* Gam = (const float*)d_in[3];
    const int*   kp  = (const int*)d_in[4];

    init_k<<<1, 512>>>();
    fused_k<<<FUSED_BLOCKS, 256>>>(Gam, SR, lsh, sig);
    gemm_k<<<NCTAS, 256>>>(Gam, SR, kp, (float*)d_out);
}